// round 3
// baseline (speedup 1.0000x reference)
#include <cuda_runtime.h>

#define D_MODEL 4096
#define D_INNER 8192
#define D_STATE 16
#define DT_RANK 8
#define XP_DIM  (DT_RANK + 2 * D_STATE)   // 40

// ---------------- scratch (device globals; no allocation allowed) ------------
__device__ float g_x_conv[D_INNER];
__device__ float g_z[D_INNER];
__device__ float g_xp[XP_DIM];
__device__ float g_y[D_INNER];
__device__ float g_h_scratch[D_INNER * D_STATE];

// ---------------- helpers ----------------------------------------------------
__device__ __forceinline__ float warp_reduce(float v) {
#pragma unroll
    for (int o = 16; o; o >>= 1) v += __shfl_xor_sync(0xffffffffu, v, o);
    return v;
}

__device__ __forceinline__ float fma4(float4 w, float4 v, float a) {
    return fmaf(w.x, v.x, fmaf(w.y, v.y, fmaf(w.z, v.z, fmaf(w.w, v.w, a))));
}

__device__ __forceinline__ float sigmoidf_(float v) { return 1.f / (1.f + expf(-v)); }

// ---------------- kernel 1: xz = W_in @ x, fused conv+silu epilogue ----------
// 16384 rows x 4096 cols. One warp per row, 8 rows per 256-thread block.
// Rows [0, 8192):  x_branch -> causal conv (4 taps, last two share x) -> silu -> g_x_conv
// Rows [8192, 16384): z -> g_z
__global__ void __launch_bounds__(256) k_gemv_in(
    const float* __restrict__ W,        // (16384, 4096)
    const float* __restrict__ x,        // (4096,)
    const float* __restrict__ cb,       // conv_buffer (8192, 3)
    const float* __restrict__ cw,       // conv_w (8192, 4)
    const float* __restrict__ conv_b)   // (8192,)
{
    const int warp = threadIdx.x >> 5, lane = threadIdx.x & 31;
    const int row = blockIdx.x * 8 + warp;

    const float4* __restrict__ Wr = (const float4*)(W + (size_t)row * D_MODEL);
    const float4* __restrict__ xv = (const float4*)x;

    float a0 = 0.f, a1 = 0.f, a2 = 0.f, a3 = 0.f;
#pragma unroll
    for (int k = 0; k < 32; k += 4) {           // 1024 float4 per row / 32 lanes
        const int b = k * 32 + lane;
        float4 w, v;
        w = Wr[b];       v = __ldg(&xv[b]);       a0 = fma4(w, v, a0);
        w = Wr[b + 32];  v = __ldg(&xv[b + 32]);  a1 = fma4(w, v, a1);
        w = Wr[b + 64];  v = __ldg(&xv[b + 64]);  a2 = fma4(w, v, a2);
        w = Wr[b + 96];  v = __ldg(&xv[b + 96]);  a3 = fma4(w, v, a3);
    }
    float acc = warp_reduce((a0 + a1) + (a2 + a3));

    if (lane == 0) {
        if (row < D_INNER) {
            // conv_in = [cb[:,1], cb[:,2], v, v] ; weights [w0,w1,w2,w3]
            const float c1 = cb[row * 3 + 1];
            const float c2 = cb[row * 3 + 2];
            const float4 w4 = *(const float4*)(cw + row * 4);
            const float s = fmaf(c1, w4.x, fmaf(c2, w4.y, fmaf(acc, w4.z + w4.w, conv_b[row])));
            g_x_conv[row] = s * sigmoidf_(s);   // silu
        } else {
            g_z[row - D_INNER] = acc;
        }
    }
}

// ---------------- kernel 2: xp = W_xp @ x_conv  (40 x 8192) ------------------
__global__ void __launch_bounds__(256) k_xp(const float* __restrict__ Wxp)
{
    const int row = blockIdx.x;                     // 0..39
    const float4* __restrict__ Wr = (const float4*)(Wxp + (size_t)row * D_INNER);
    const float4* __restrict__ xc = (const float4*)g_x_conv;

    float acc = 0.f;
    for (int idx = threadIdx.x; idx < D_INNER / 4; idx += 256) {
        acc = fma4(Wr[idx], xc[idx], acc);
    }
    __shared__ float sred[8];
    acc = warp_reduce(acc);
    if ((threadIdx.x & 31) == 0) sred[threadIdx.x >> 5] = acc;
    __syncthreads();
    if (threadIdx.x < 32) {
        float v = (threadIdx.x < 8) ? sred[threadIdx.x] : 0.f;
        v = warp_reduce(v);
        if (threadIdx.x == 0) g_xp[row] = v;
    }
}

// ---------------- kernel 3: dt/softplus + SSM state update + gate ------------
// One thread per channel (8192). Writes new_h and g_y.
__global__ void __launch_bounds__(256) k_state(
    const float* __restrict__ Wdt,      // (8192, 8)
    const float* __restrict__ bdt,      // (8192,)
    const float* __restrict__ Alog,     // (8192, 16)
    const float* __restrict__ h,        // ssm_state (8192, 16)
    const float* __restrict__ Dp,       // (8192,)
    float* __restrict__ newh)           // (8192, 16) or nullptr
{
    const int i = blockIdx.x * 256 + threadIdx.x;

    __shared__ float sxp[XP_DIM];
    if (threadIdx.x < XP_DIM) sxp[threadIdx.x] = g_xp[threadIdx.x];
    __syncthreads();

    // dt = softplus(W_dt[i,:] . xp[:8] + b_dt[i])
    const float4* wd = (const float4*)(Wdt + (size_t)i * DT_RANK);
    const float4 w0 = wd[0], w1 = wd[1];
    float dtin = bdt[i];
    dtin += w0.x * sxp[0] + w0.y * sxp[1] + w0.z * sxp[2] + w0.w * sxp[3]
          + w1.x * sxp[4] + w1.y * sxp[5] + w1.z * sxp[6] + w1.w * sxp[7];
    const float dt = (dtin > 20.f) ? dtin : log1pf(expf(dtin));

    const float xc = g_x_conv[i];
    const float* Ar = Alog + (size_t)i * D_STATE;
    const float* hr = h    + (size_t)i * D_STATE;
    float* nr = (newh ? newh : g_h_scratch) + (size_t)i * D_STATE;

    float acc = 0.f;
#pragma unroll
    for (int s = 0; s < D_STATE; s++) {
        const float abar = expf(-dt * expf(Ar[s]));               // exp(dt * -exp(A_log))
        const float nh = fmaf(abar, hr[s], dt * sxp[DT_RANK + s] * xc);
        nr[s] = nh;
        acc = fmaf(nh, sxp[DT_RANK + D_STATE + s], acc);
    }
    const float y = acc + Dp[i] * xc;
    const float z = g_z[i];
    g_y[i] = y * (z * sigmoidf_(z));
}

// ---------------- kernel 4: out = W_out @ y  (4096 x 8192) -------------------
__global__ void __launch_bounds__(256) k_gemv_out(
    const float* __restrict__ W, float* __restrict__ out)
{
    const int warp = threadIdx.x >> 5, lane = threadIdx.x & 31;
    const int row = blockIdx.x * 8 + warp;

    const float4* __restrict__ Wr = (const float4*)(W + (size_t)row * D_INNER);
    const float4* __restrict__ yv = (const float4*)g_y;

    float a0 = 0.f, a1 = 0.f, a2 = 0.f, a3 = 0.f;
#pragma unroll
    for (int k = 0; k < 64; k += 4) {           // 2048 float4 per row / 32 lanes
        const int b = k * 32 + lane;
        float4 w, v;
        w = Wr[b];       v = __ldg(&yv[b]);       a0 = fma4(w, v, a0);
        w = Wr[b + 32];  v = __ldg(&yv[b + 32]);  a1 = fma4(w, v, a1);
        w = Wr[b + 64];  v = __ldg(&yv[b + 64]);  a2 = fma4(w, v, a2);
        w = Wr[b + 96];  v = __ldg(&yv[b + 96]);  a3 = fma4(w, v, a3);
    }
    float acc = warp_reduce((a0 + a1) + (a2 + a3));
    if (lane == 0) out[row] = acc;
}

// ---------------- launch ------------------------------------------------------
extern "C" void kernel_launch(void* const* d_in, const int* in_sizes, int n_in,
                              void* d_out, int out_size)
{
    const float* x       = (const float*)d_in[0];
    const float* h       = (const float*)d_in[1];   // ssm_state
    const float* cb      = (const float*)d_in[2];   // conv_buffer
    const float* W_in    = (const float*)d_in[3];
    const float* conv_w  = (const float*)d_in[4];
    const float* conv_b  = (const float*)d_in[5];
    const float* W_xp    = (const float*)d_in[6];
    const float* W_dt    = (const float*)d_in[7];
    const float* b_dt    = (const float*)d_in[8];
    const float* A_log   = (const float*)d_in[9];
    const float* D_param = (const float*)d_in[10];
    const float* W_out   = (const float*)d_in[11];

    float* out = (float*)d_out;
    // tuple output (out, new_h) concatenated: [4096][8192*16]
    float* newh = (out_size >= D_MODEL + D_INNER * D_STATE) ? (out + D_MODEL) : nullptr;

    k_gemv_in <<<(2 * D_INNER) / 8, 256>>>(W_in, x, cb, conv_w, conv_b);
    k_xp      <<<XP_DIM, 256>>>(W_xp);
    k_state   <<<D_INNER / 256, 256>>>(W_dt, b_dt, A_log, h, D_param, newh);
    k_gemv_out<<<D_MODEL / 8, 256>>>(W_out, out);
}